// round 5
// baseline (speedup 1.0000x reference)
#include <cuda_runtime.h>
#include <cstdint>

// RLFrameSelector R5: scores GEMM on tensor cores via legacy mma.sync tf32
// (m16n8k8), 3xTF32 split for fp32-class accuracy. tcgen05 is unavailable at
// the harness's compile target (sm_100 non-'a'), so this is the tensor path.

#define BB 32
#define TT 2048
#define FF 512
#define UU 128
#define CTM 128               // frames per CTA
#define KC 16                 // K per chunk
#define NCH (FF / KC)         // 32
#define AST 20                // A smem row stride (floats) -> conflict-free frags

// smem float offsets
#define FA0  0                // A buf0: 128*20 = 2560
#define FA1  2560
#define FBH0 5120             // B-hi buf0: 2*8*32*4 = 2048
#define FBH1 7168
#define FBL0 9216
#define FBL1 11264
#define SMF  13312            // total floats
#define SMEMB (SMF * 4)       // 53248 bytes
// epilogue aliases (A0 region, dead after last chunk):
//   red = sm[0..255]  (2 x 128 floats), nzf = (int*)(sm+256) [128]

__device__ float         g_scores[BB * TT];
__device__ unsigned char g_sel[BB * TT];
__device__ float         g_Bh[FF * UU];   // W1 split-hi, mma-fragment order
__device__ float         g_Bl[FF * UU];   // W1 split-lo, mma-fragment order

__device__ __forceinline__ uint32_t tf32_u(float x) {
    uint32_t r;
    asm("cvt.rna.tf32.f32 %0, %1;" : "=r"(r) : "f"(x));
    return r;
}

__device__ __forceinline__ void mma8(float d[4], const uint32_t a[4],
                                     uint32_t b0, uint32_t b1) {
    asm volatile(
        "mma.sync.aligned.m16n8k8.row.col.f32.tf32.tf32.f32 "
        "{%0,%1,%2,%3}, {%4,%5,%6,%7}, {%8,%9}, {%0,%1,%2,%3};"
        : "+f"(d[0]), "+f"(d[1]), "+f"(d[2]), "+f"(d[3])
        : "r"(a[0]), "r"(a[1]), "r"(a[2]), "r"(a[3]), "r"(b0), "r"(b1));
}

// ---------------------------------------------------------------------------
// prep: W1 [k=512][n=128] -> hi/lo tf32 in fragment-order global layout:
// widx = (((c*2+ks)*8 + npg)*32 + lane)*4 + w
//   k = 16c + 8ks + (lane&3) + 4*(w&1),  n = 16*npg + 8*(w>>1) + (lane>>2)
// ---------------------------------------------------------------------------
__global__ __launch_bounds__(256) void prep_b(const float* __restrict__ W1)
{
    const int widx = blockIdx.x * 256 + threadIdx.x;     // 0..65535
    const int w    = widx & 3;
    const int lane = (widx >> 2) & 31;
    const int npg  = (widx >> 7) & 7;
    const int ksc  = widx >> 10;                         // 0..63
    const int k = 16 * (ksc >> 1) + 8 * (ksc & 1) + (lane & 3) + 4 * (w & 1);
    const int n = 16 * npg + 8 * (w >> 1) + (lane >> 2);
    const float v  = W1[k * UU + n];
    const uint32_t hu = tf32_u(v);
    const float hf = __uint_as_float(hu);
    g_Bh[widx] = hf;
    g_Bl[widx] = __uint_as_float(tf32_u(v - hf));
}

// ---------------------------------------------------------------------------
// score: 512 threads, 16 warps. warp m0=(wid&7)*16, nw=wid>>3 (64 units).
// Per k8 step/warp: 4 LDS.32 A (conflict-free) + split, 8 LDS.128 B, 24 mma.
// ---------------------------------------------------------------------------
__global__ __launch_bounds__(512) void score_kernel(
    const float* __restrict__ x,  const float* __restrict__ b1,
    const float* __restrict__ W2, const float* __restrict__ b2)
{
    extern __shared__ float sm[];
    const int tid  = threadIdx.x;
    const int lane = tid & 31;
    const int wid  = tid >> 5;
    const int g    = lane >> 2;
    const int t    = lane & 3;
    const int nw   = wid >> 3;            // 0,1 -> unit half
    const int m0   = (wid & 7) * 16;      // frame base within CTA
    const int frame0 = blockIdx.x * CTM;
    const int arow = tid >> 2;            // 0..127 (one x row per thread)
    const int ac   = tid & 3;             // float4 group within chunk

    float acc[8][4];
#pragma unroll
    for (int i = 0; i < 8; ++i)
#pragma unroll
        for (int j = 0; j < 4; ++j) acc[i][j] = 0.0f;

    const float* xrow = x + (size_t)(frame0 + arow) * FF + 4 * ac;
    const float4* bh4 = (const float4*)g_Bh;
    const float4* bl4 = (const float4*)g_Bl;

    unsigned nzb = 0;

    // ---- prologue: chunk 0 -> buf 0
    float4 av = *(const float4*)(xrow);
    float4 hv = bh4[tid];
    float4 lv = bl4[tid];
    nzb |= (av.x != 0.f) | (av.y != 0.f) | (av.z != 0.f) | (av.w != 0.f);
    *(float4*)&sm[FA0 + arow * AST + 4 * ac] = av;
    ((float4*)(sm + FBH0))[tid] = hv;
    ((float4*)(sm + FBL0))[tid] = lv;
    __syncthreads();

#pragma unroll 1
    for (int c = 0; c < NCH; ++c) {
        const int  buf  = c & 1;
        const bool more = (c + 1 < NCH);
        if (more) {
            av = *(const float4*)(xrow + (c + 1) * KC);
            hv = bh4[(c + 1) * 512 + tid];
            lv = bl4[(c + 1) * 512 + tid];
        }
        const float* As = sm + (buf ? FA1 : FA0);
        const float* Bh = sm + (buf ? FBH1 : FBH0);
        const float* Bl = sm + (buf ? FBL1 : FBL0);

#pragma unroll
        for (int ks = 0; ks < 2; ++ks) {
            uint32_t ah[4], al[4];
            {
                const int ro = (m0 + g) * AST + 8 * ks + t;
                const float r0 = As[ro];
                const float r1 = As[ro + 8 * AST];
                const float r2 = As[ro + 4];
                const float r3 = As[ro + 8 * AST + 4];
                ah[0] = tf32_u(r0); al[0] = tf32_u(r0 - __uint_as_float(ah[0]));
                ah[1] = tf32_u(r1); al[1] = tf32_u(r1 - __uint_as_float(ah[1]));
                ah[2] = tf32_u(r2); al[2] = tf32_u(r2 - __uint_as_float(ah[2]));
                ah[3] = tf32_u(r3); al[3] = tf32_u(r3 - __uint_as_float(ah[3]));
            }
#pragma unroll
            for (int np = 0; np < 4; ++np) {
                const int fo = ((ks * 8 + 4 * nw + np) * 32 + lane) * 4;
                const float4 bh = *(const float4*)&Bh[fo];
                const float4 bl = *(const float4*)&Bl[fo];
                const uint32_t h0 = __float_as_uint(bh.x);
                const uint32_t h1 = __float_as_uint(bh.y);
                const uint32_t h2 = __float_as_uint(bh.z);
                const uint32_t h3 = __float_as_uint(bh.w);
                const uint32_t l0 = __float_as_uint(bl.x);
                const uint32_t l1 = __float_as_uint(bl.y);
                const uint32_t l2 = __float_as_uint(bl.z);
                const uint32_t l3 = __float_as_uint(bl.w);
                mma8(acc[2 * np],     ah, h0, h1);
                mma8(acc[2 * np],     ah, l0, l1);
                mma8(acc[2 * np],     al, h0, h1);
                mma8(acc[2 * np + 1], ah, h2, h3);
                mma8(acc[2 * np + 1], ah, l2, l3);
                mma8(acc[2 * np + 1], al, h2, h3);
            }
        }

        if (more) {
            nzb |= (av.x != 0.f) | (av.y != 0.f) | (av.z != 0.f) | (av.w != 0.f);
            const int nb = buf ^ 1;
            *(float4*)&sm[(nb ? FA1 : FA0) + arow * AST + 4 * ac] = av;
            ((float4*)(sm + (nb ? FBH1 : FBH0)))[tid] = hv;
            ((float4*)(sm + (nb ? FBL1 : FBL0)))[tid] = lv;
        }
        __syncthreads();
    }

    // ---- nz mask: OR over the 4 threads sharing a row (lanes differ in t)
    unsigned nzv = nzb;
    nzv |= __shfl_xor_sync(0xFFFFFFFFu, nzv, 1);
    nzv |= __shfl_xor_sync(0xFFFFFFFFu, nzv, 2);

    // ---- epilogue: relu + W2 dot; reduce over t-lanes, then over nw
    float p0 = 0.0f, p1 = 0.0f;
#pragma unroll
    for (int ntl = 0; ntl < 8; ++ntl) {
        const int cb = nw * 64 + 8 * ntl + 2 * t;
        const float w2a = __ldg(W2 + cb), w2b = __ldg(W2 + cb + 1);
        const float ba  = __ldg(b1 + cb), bb  = __ldg(b1 + cb + 1);
        p0 += fmaxf(acc[ntl][0] + ba, 0.f) * w2a
            + fmaxf(acc[ntl][1] + bb, 0.f) * w2b;
        p1 += fmaxf(acc[ntl][2] + ba, 0.f) * w2a
            + fmaxf(acc[ntl][3] + bb, 0.f) * w2b;
    }
    p0 += __shfl_xor_sync(0xFFFFFFFFu, p0, 1);
    p0 += __shfl_xor_sync(0xFFFFFFFFu, p0, 2);
    p1 += __shfl_xor_sync(0xFFFFFFFFu, p1, 1);
    p1 += __shfl_xor_sync(0xFFFFFFFFu, p1, 2);

    float* red = sm;                       // 256 floats (A0 region, now dead)
    int*   nzf = (int*)(sm + 256);         // 128 ints
    if (t == 0) {
        red[nw * 128 + m0 + g]     = p0;
        red[nw * 128 + m0 + 8 + g] = p1;
        nzf[arow] = 0;                     // placeholder; real write below
    }
    __syncthreads();
    if (t == 0) { /* nz writers: lane t==0 of each row group */ }
    if ((tid & 3) == 0) nzf[arow] = (int)(nzv & 1u);
    __syncthreads();

    if (tid < CTM) {
        const float s = red[tid] + red[128 + tid] + __ldg(b2);
        g_scores[frame0 + tid] = nzf[tid] ? s : -1.0e9f;
    }
}

// ---------------------------------------------------------------------------
// Kernel 2: per-batch top-k via 4x8-bit radix select (stable tie-break).
// ---------------------------------------------------------------------------
__global__ __launch_bounds__(256) void topk_kernel(const int* kptr)
{
    __shared__ unsigned keys[TT];
    __shared__ int      hist[256];
    __shared__ unsigned s_prefix;
    __shared__ int      s_remaining;

    const int b   = blockIdx.x;
    const int tid = threadIdx.x;

    int k = 64;
    if (kptr) {
        int kv = *kptr;
        if (kv > 0 && kv <= TT) k = kv;
        else {
            float kf = __int_as_float(kv);
            if (kf >= 1.0f && kf <= (float)TT) k = (int)kf;
        }
    }

    for (int i = tid; i < TT; i += 256) {
        unsigned u = __float_as_uint(g_scores[b * TT + i]);
        keys[i] = (u & 0x80000000u) ? ~u : (u | 0x80000000u);
    }
    if (tid == 0) { s_prefix = 0u; s_remaining = k; }
    __syncthreads();

    for (int pass = 3; pass >= 0; --pass) {
        hist[tid] = 0;
        __syncthreads();
        const unsigned mhi  = (pass == 3) ? 0u : (0xFFFFFFFFu << ((pass + 1) * 8));
        const unsigned pref = s_prefix;
        const int shift = pass * 8;
        for (int i = tid; i < TT; i += 256) {
            const unsigned ky = keys[i];
            if ((ky & mhi) == pref) atomicAdd(&hist[(ky >> shift) & 255], 1);
        }
        __syncthreads();
        if (tid == 0) {
            int rem = s_remaining, cum = 0, bin;
            for (bin = 255; bin >= 0; --bin) {
                const int c = hist[bin];
                if (cum + c >= rem) break;
                cum += c;
            }
            s_prefix    = pref | ((unsigned)bin << shift);
            s_remaining = rem - cum;
        }
        __syncthreads();
    }

    const unsigned thr = s_prefix;
    const int need = s_remaining;
    for (int i = tid; i < TT; i += 256) {
        const unsigned ky = keys[i];
        unsigned char sv = 0;
        if (ky > thr) sv = 1;
        else if (ky == thr) {
            int r = 0;
            for (int j = 0; j < i; ++j) r += (keys[j] == thr);
            sv = (r < need) ? 1 : 0;
        }
        g_sel[b * TT + i] = sv;
    }
}

// ---------------------------------------------------------------------------
// Kernel 3: out = sel ? x : 0.
// ---------------------------------------------------------------------------
__global__ __launch_bounds__(256) void gather_kernel(
    const float* __restrict__ x, float* __restrict__ out)
{
    const int i = blockIdx.x * 256 + threadIdx.x;   // float4 index
    const int frame = i >> 7;                       // 128 float4 per frame
    float4 v = make_float4(0.f, 0.f, 0.f, 0.f);
    if (g_sel[frame]) v = ((const float4*)x)[i];
    ((float4*)out)[i] = v;
}

// ---------------------------------------------------------------------------
extern "C" void kernel_launch(void* const* d_in, const int* in_sizes, int n_in,
                              void* d_out, int out_size)
{
    const float* x  = (const float*)d_in[0];
    const float* W1 = (const float*)d_in[1];
    const float* b1 = (const float*)d_in[2];
    const float* W2 = (const float*)d_in[3];
    const float* b2 = (const float*)d_in[4];
    const int*   kp = (n_in > 5) ? (const int*)d_in[5] : nullptr;

    cudaFuncSetAttribute(score_kernel,
                         cudaFuncAttributeMaxDynamicSharedMemorySize, SMEMB);

    prep_b<<<(FF * UU) / 256, 256>>>(W1);
    score_kernel<<<(BB * TT) / CTM, 512, SMEMB>>>(x, b1, W2, b2);
    topk_kernel<<<BB, 256>>>(kp);
    gather_kernel<<<(BB * TT * FF / 4) / 256, 256>>>(x, (float*)d_out);
}